// round 8
// baseline (speedup 1.0000x reference)
#include <cuda_runtime.h>
#include <cuda_fp16.h>
#include <cstdint>
#include <cstddef>

#define N_NODES 20000
#define N_EDGES 160000
#define MUL0 32
#define MUL1 16
#define NODE_DIM 80
#define EDGE_FEAT 128
#define HIDDEN 128
#define W_NUMEL 2560
#define MTILE 128
#define NTILES (N_EDGES / MTILE)      // 1250
#define NCHUNK 128
#define NCHUNKS (W_NUMEL / NCHUNK)    // 20

#define C0f   0.14433756729740643f
#define C1f   0.21650635094610965f
#define IS3f  0.5773502691896258f
#define IS6f  0.40824829046386296f
#define C0IS3 (C0f * IS3f)
#define C1IS3 (C1f * IS3f)
#define C1IS6 (C1f * IS6f)
#define EPS_LN 1e-5f

// ---------------- device scratch ----------------
__device__ __align__(16) __half g_A[(size_t)N_EDGES * HIDDEN];     // h fp16, [e][k]
__device__ __align__(16) __half g_Bf16[(size_t)W_NUMEL * HIDDEN];  // W2^T fp16 [n][k]
__device__ float g_seg[(size_t)N_NODES * NODE_DIM];
__device__ float g_cnt[N_NODES];

// ---------------- PTX helpers ----------------
__device__ __forceinline__ uint32_t smem_u32(const void* p) {
    uint32_t a;
    asm("{ .reg .u64 t; cvta.to.shared.u64 t, %1; cvt.u32.u64 %0, t; }" : "=r"(a) : "l"(p));
    return a;
}
__device__ __forceinline__ void ldsm_x4(uint32_t* r, uint32_t addr) {
    asm volatile("ldmatrix.sync.aligned.m8n8.x4.shared.b16 {%0,%1,%2,%3}, [%4];"
        : "=r"(r[0]), "=r"(r[1]), "=r"(r[2]), "=r"(r[3]) : "r"(addr));
}
__device__ __forceinline__ void mma_f16(float* c, const uint32_t* a, uint32_t b0, uint32_t b1) {
    asm volatile("mma.sync.aligned.m16n8k16.row.col.f32.f16.f16.f32 "
        "{%0,%1,%2,%3}, {%4,%5,%6,%7}, {%8,%9}, {%0,%1,%2,%3};"
        : "+f"(c[0]), "+f"(c[1]), "+f"(c[2]), "+f"(c[3])
        : "r"(a[0]), "r"(a[1]), "r"(a[2]), "r"(a[3]), "r"(b0), "r"(b1));
}
__device__ __forceinline__ void cp_async16(uint32_t smem_addr, const void* gptr) {
    asm volatile("cp.async.ca.shared.global [%0], [%1], 16;" :: "r"(smem_addr), "l"(gptr));
}
#define CP_COMMIT() asm volatile("cp.async.commit_group;" ::: "memory")
#define CP_WAIT_0() asm volatile("cp.async.wait_group 0;" ::: "memory")

#define ROWB 272

// ---------------- GEMM1 (fp16 2-pass A hi/lo) + embedded prep ----------------
#define G1_AHI 0
#define G1_ALO 34816
#define G1_W   69632
#define G1_B1  104448
#define G1_SMEM 104960

__global__ __launch_bounds__(256, 2)
void gemm1_kernel(const float* __restrict__ edge_attr,
                  const float* __restrict__ fc_w1,
                  const float* __restrict__ fc_b1,
                  const float* __restrict__ fc_w2) {
    extern __shared__ char smc[];
    const uint32_t smb = smem_u32(smc);
    const int tid = threadIdx.x;
    const int w = tid >> 5;
    const int lane = tid & 31;
    const int e0 = blockIdx.x * 128;

    // embedded prep (block-strided)
    {
        const int gt = blockIdx.x * 256 + tid;
        const int gs = gridDim.x * 256;
        for (int i = gt; i < N_NODES * NODE_DIM; i += gs) g_seg[i] = 0.0f;
        for (int i = gt; i < N_NODES; i += gs) g_cnt[i] = 0.0f;
        for (int i = gt; i < HIDDEN * W_NUMEL; i += gs) {
            const int n = i >> 7, k = i & 127;
            g_Bf16[i] = __float2half_rn(fc_w2[(size_t)k * W_NUMEL + n]);
        }
    }

    // W1 fp32 -> fp16 transposed into SMEM
    for (int i = tid; i < HIDDEN * HIDDEN; i += 256) {
        const int k = i >> 7, n = i & 127;
        *(__half*)(smc + G1_W + n * ROWB + k * 2) = __float2half_rn(fc_w1[i]);
    }

    // stage A: fp32 -> fp16 hi/lo
    const float4* ga = (const float4*)(edge_attr + (size_t)e0 * EDGE_FEAT);
#pragma unroll
    for (int it = 0; it < 16; it++) {
        const int i = tid + it * 256;
        const int row = i >> 5, kc4 = i & 31;
        const float4 v = ga[i];
        const __half hx = __float2half_rn(v.x), hy = __float2half_rn(v.y);
        const __half hz = __float2half_rn(v.z), hw = __float2half_rn(v.w);
        const __half lx = __float2half_rn(v.x - __half2float(hx));
        const __half ly = __float2half_rn(v.y - __half2float(hy));
        const __half lz = __float2half_rn(v.z - __half2float(hz));
        const __half lw = __float2half_rn(v.w - __half2float(hw));
        char* dh = smc + G1_AHI + row * ROWB + kc4 * 8;
        char* dl = smc + G1_ALO + row * ROWB + kc4 * 8;
        *(__half2*)(dh)     = __halves2half2(hx, hy);
        *(__half2*)(dh + 4) = __halves2half2(hz, hw);
        *(__half2*)(dl)     = __halves2half2(lx, ly);
        *(__half2*)(dl + 4) = __halves2half2(lz, lw);
    }
    if (tid < 128) ((float*)(smc + G1_B1))[tid] = fc_b1[tid];
    __syncthreads();

    const int q2 = 2 * (lane & 3);
    const int r8 = lane >> 2;
    const int mA = 16 * w + r8;

    const uint32_t aRow = (uint32_t)(16 * w + (lane & 7) + ((lane >> 3) & 1) * 8);
    const uint32_t aK = (uint32_t)(((lane >> 4) & 1) * 16);
    const uint32_t aHiB = smb + G1_AHI + aRow * ROWB + aK;
    const uint32_t aLoB = smb + G1_ALO + aRow * ROWB + aK;
    const uint32_t bRow = (uint32_t)((lane & 7) + ((lane >> 4) & 1) * 8);
    const uint32_t bK = (uint32_t)(((lane >> 3) & 1) * 16);
    const uint32_t wB = smb + G1_W + bRow * ROWB + bK;

    float c[16][4];
#pragma unroll
    for (int t = 0; t < 16; t++)
#pragma unroll
        for (int i = 0; i < 4; i++) c[t][i] = 0.0f;

#pragma unroll
    for (int ks = 0; ks < 8; ks++) {
        uint32_t ah[4], al[4];
        ldsm_x4(ah, aHiB + ks * 32);
        ldsm_x4(al, aLoB + ks * 32);
#pragma unroll
        for (int tp = 0; tp < 8; tp++) {
            uint32_t wf[4];
            ldsm_x4(wf, wB + tp * (16 * ROWB) + ks * 32);
            mma_f16(c[2 * tp],     ah, wf[0], wf[1]);
            mma_f16(c[2 * tp],     al, wf[0], wf[1]);
            mma_f16(c[2 * tp + 1], ah, wf[2], wf[3]);
            mma_f16(c[2 * tp + 1], al, wf[2], wf[3]);
        }
    }

    const float* b1s = (const float*)(smc + G1_B1);
#pragma unroll
    for (int t = 0; t < 16; t++) {
        const int col = 8 * t + q2;
        const float bb0 = b1s[col], bb1 = b1s[col + 1];
#pragma unroll
        for (int rr = 0; rr < 2; rr++) {
            const int mm = mA + 8 * rr;
            const float v0 = fmaxf(c[t][2 * rr + 0] + bb0, 0.0f);
            const float v1 = fmaxf(c[t][2 * rr + 1] + bb1, 0.0f);
            *(__half2*)(g_A + (size_t)(e0 + mm) * HIDDEN + col) =
                __halves2half2(__float2half_rn(v0), __float2half_rn(v1));
        }
    }
}

// ---------------- edge kernel: A-in-regs, NCHUNK=128, 2-stage ring ----------------
// SMEM: stage0 @0 (34816, holds A during prologue), stage1 @34816.
// Chunk j lives at stage ((j+1)&1). Tables: x0s@69632, x1s@86528, shs@111616, srcs@113664.
#define BSTG    34816
#define OFF_X0  69632
#define OFF_X1  86528
#define OFF_SH  111616
#define OFF_SRC 113664
#define EDGE_SMEM 114176

#define PREFETCH128(jn) \
    if ((jn) < NCHUNKS) { \
        const uint32_t sb = smb + (uint32_t)((((jn) + 1) & 1) * BSTG); \
        const __half* gp0 = g_Bf16 + (size_t)(jn) * NCHUNK * HIDDEN; \
        _Pragma("unroll") \
        for (int it = 0; it < 8; it++) { \
            const int i = tid + it * 256; \
            const int row = i >> 4, kc = i & 15; \
            cp_async16(sb + row * ROWB + kc * 16, gp0 + (size_t)row * HIDDEN + kc * 8); \
        } \
        CP_COMMIT(); \
    }

#define CHUNK_TOP(j) \
    CP_WAIT_0(); \
    __syncthreads(); \
    PREFETCH128((j) + 1)

// MMA for 32-col sub-tile s of chunk j: B rows [64*cg + 32*s, +32)
#define CHUNK_MMA_SUB(j, s) \
    float c[2][4][4]; \
    { \
        _Pragma("unroll") for (int rt = 0; rt < 2; rt++) \
        _Pragma("unroll") for (int nt = 0; nt < 4; nt++) \
        _Pragma("unroll") for (int i = 0; i < 4; i++) c[rt][nt][i] = 0.0f; \
        const uint32_t bb = smb + (uint32_t)((((j) + 1) & 1) * BSTG) \
                          + (uint32_t)(64 * cg + 32 * (s)) * ROWB + bRowOff; \
        _Pragma("unroll") for (int ks = 0; ks < 8; ks++) { \
            _Pragma("unroll") for (int tp = 0; tp < 2; tp++) { \
                uint32_t bf[4]; \
                ldsm_x4(bf, bb + tp * (16 * ROWB) + ks * 32); \
                _Pragma("unroll") for (int rt = 0; rt < 2; rt++) { \
                    mma_f16(c[rt][2 * tp],     a_[rt][ks], bf[0], bf[1]); \
                    mma_f16(c[rt][2 * tp + 1], a_[rt][ks], bf[2], bf[3]); \
                } \
            } \
        } \
    }

#define LOAD_B2V(g) \
    float b2v[4][2]; \
    _Pragma("unroll") for (int nt = 0; nt < 4; nt++) { \
        const float2 bv = __ldg((const float2*)(fc_b2 + 32 * (g) + 8 * nt + q2)); \
        b2v[nt][0] = bv.x; b2v[nt][1] = bv.y; \
    }

__global__ __launch_bounds__(256, 1)
void edge_kernel(const float* __restrict__ node_attr,
                 const float* __restrict__ edge_sh,
                 const float* __restrict__ fc_b2,
                 const int*   __restrict__ edge_index) {
    extern __shared__ char smc[];
    const uint32_t smb = smem_u32(smc);
    float* x0s = (float*)(smc + OFF_X0);
    float* x1s = (float*)(smc + OFF_X1);
    float* shs = (float*)(smc + OFF_SH);
    int*  srcs = (int*)(smc + OFF_SRC);

    const int tid  = threadIdx.x;
    const int w    = tid >> 5;
    const int lane = tid & 31;
    const int rg   = w >> 1;       // row group: rows 32rg..32rg+31
    const int cg   = w & 1;        // 64-col half of the 128-col chunk
    const int e0 = blockIdx.x * MTILE;

    // ---- prologue cp.async: A -> stage0, B chunk0 -> stage1 ----
#pragma unroll
    for (int it = 0; it < 8; it++) {
        const int i = tid + it * 256;       // row(128) x kc(16)
        const int row = i >> 4, kc = i & 15;
        cp_async16(smb + row * ROWB + kc * 16,
                   g_A + (size_t)(e0 + row) * HIDDEN + kc * 8);
    }
#pragma unroll
    for (int it = 0; it < 8; it++) {        // B chunk 0 -> stage1
        const int i = tid + it * 256;       // row(128) x kc(16)
        const int row = i >> 4, kc = i & 15;
        cp_async16(smb + BSTG + row * ROWB + kc * 16,
                   g_Bf16 + (size_t)row * HIDDEN + kc * 8);
    }
    CP_COMMIT();

    // ---- gather per-edge vectors ----
    if (tid < MTILE) {
        const int eg  = e0 + tid;
        const int src = edge_index[eg];
        const int dst = edge_index[N_EDGES + eg];
        srcs[tid] = src;
        atomicAdd(&g_cnt[src], 1.0f);
        const float4* na = (const float4*)(node_attr + (size_t)dst * NODE_DIM);
#pragma unroll
        for (int q = 0; q < 8; q++) {
            const float4 v = na[q];
            x0s[tid * 33 + 4 * q + 0] = v.x;
            x0s[tid * 33 + 4 * q + 1] = v.y;
            x0s[tid * 33 + 4 * q + 2] = v.z;
            x0s[tid * 33 + 4 * q + 3] = v.w;
        }
#pragma unroll
        for (int q = 0; q < 12; q++) {
            const float4 v = na[8 + q];
            x1s[tid * 49 + 4 * q + 0] = v.x;
            x1s[tid * 49 + 4 * q + 1] = v.y;
            x1s[tid * 49 + 4 * q + 2] = v.z;
            x1s[tid * 49 + 4 * q + 3] = v.w;
        }
        const float4 sh4 = *(const float4*)(edge_sh + (size_t)eg * 4);
        shs[tid * 4 + 0] = sh4.x;
        shs[tid * 4 + 1] = sh4.y;
        shs[tid * 4 + 2] = sh4.z;
        shs[tid * 4 + 3] = sh4.w;
    }

    CP_WAIT_0();            // A + B0 landed (own copies)
    __syncthreads();        // visibility for all warps

    // ---- A frags -> registers ----
    const int q2 = 2 * (lane & 3);
    const int r8 = lane >> 2;
    const uint32_t aRowLoc = (uint32_t)((lane & 7) + 8 * ((lane >> 3) & 1));
    const uint32_t aK = (uint32_t)(16 * ((lane >> 4) & 1));
    uint32_t a_[2][8][4];
#pragma unroll
    for (int rt = 0; rt < 2; rt++) {
        const uint32_t base = smb + (uint32_t)((32 * rg + 16 * rt) + aRowLoc) * ROWB + aK;
#pragma unroll
        for (int ks = 0; ks < 8; ks++)
            ldsm_x4(a_[rt][ks], base + ks * 32);
    }
    __syncthreads();        // all warps done with A region before it becomes a B stage

    const uint32_t bRowOff = (uint32_t)((lane & 7) + 8 * ((lane >> 4) & 1)) * ROWB
                           + (uint32_t)(16 * ((lane >> 3) & 1));

    int mm[4];
#pragma unroll
    for (int r = 0; r < 4; r++) mm[r] = 32 * rg + 16 * (r >> 1) + 8 * (r & 1) + r8;

    // ================= phase 1: j 0..11 (g < 48) -> accO =================
    {
        float accO[4][8];
#pragma unroll
        for (int r = 0; r < 4; r++)
#pragma unroll
            for (int i = 0; i < 8; i++) accO[r][i] = 0.0f;

        for (int j = 0; j < 12; j++) {
            CHUNK_TOP(j);
#pragma unroll
            for (int s = 0; s < 2; s++) {
                CHUNK_MMA_SUB(j, s);
                const int g = 4 * j + 2 * cg + s;
                LOAD_B2V(g);
                float sc[4];
                if (g < 32) {
#pragma unroll
                    for (int r = 0; r < 4; r++)
                        sc[r] = C0f * shs[mm[r] * 4] * x0s[mm[r] * 33 + g];
                } else {
                    const int u = g - 32;
#pragma unroll
                    for (int r = 0; r < 4; r++)
                        sc[r] = C0IS3 * (x1s[mm[r] * 49 + 3 * u]     * shs[mm[r] * 4 + 1]
                                       + x1s[mm[r] * 49 + 3 * u + 1] * shs[mm[r] * 4 + 2]
                                       + x1s[mm[r] * 49 + 3 * u + 2] * shs[mm[r] * 4 + 3]);
                }
#pragma unroll
                for (int nt = 0; nt < 4; nt++)
#pragma unroll
                    for (int rt = 0; rt < 2; rt++)
#pragma unroll
                        for (int rr = 0; rr < 2; rr++)
#pragma unroll
                            for (int b = 0; b < 2; b++)
                                accO[2 * rt + rr][2 * nt + b] +=
                                    sc[2 * rt + rr] * (c[rt][nt][2 * rr + b] + b2v[nt][b]);
            }
        }
#pragma unroll
        for (int r = 0; r < 4; r++) {
            float* segp = g_seg + (size_t)srcs[mm[r]] * NODE_DIM;
#pragma unroll
            for (int nt = 0; nt < 4; nt++)
#pragma unroll
                for (int b = 0; b < 2; b++)
                    atomicAdd(segp + 8 * nt + q2 + b, accO[r][2 * nt + b]);
        }
    }

    // ================= phase 2: j 12..15 (g 48..63) -> t3 =================
    {
        float accT3[4][4];
#pragma unroll
        for (int r = 0; r < 4; r++)
#pragma unroll
            for (int i = 0; i < 4; i++) accT3[r][i] = 0.0f;

        for (int j = 12; j < 16; j++) {
            CHUNK_TOP(j);
#pragma unroll
            for (int s = 0; s < 2; s++) {
                CHUNK_MMA_SUB(j, s);
                const int g = 4 * j + 2 * cg + s;
                LOAD_B2V(g);
                const int u0 = 2 * (g - 48);
                float sc[4][2];
#pragma unroll
                for (int r = 0; r < 4; r++) {
                    sc[r][0] = C1IS3 * x0s[mm[r] * 33 + u0];
                    sc[r][1] = C1IS3 * x0s[mm[r] * 33 + u0 + 1];
                }
#pragma unroll
                for (int nt = 0; nt < 4; nt++) {
                    const int us = nt >> 1, ws = nt & 1;
#pragma unroll
                    for (int rt = 0; rt < 2; rt++)
#pragma unroll
                        for (int rr = 0; rr < 2; rr++)
#pragma unroll
                            for (int b = 0; b < 2; b++)
                                accT3[2 * rt + rr][2 * ws + b] +=
                                    sc[2 * rt + rr][us] * (c[rt][nt][2 * rr + b] + b2v[nt][b]);
                }
            }
        }
#pragma unroll
        for (int r = 0; r < 4; r++) {
            float* segp = g_seg + (size_t)srcs[mm[r]] * NODE_DIM;
            const float s1x = shs[mm[r] * 4 + 1];
            const float s1y = shs[mm[r] * 4 + 2];
            const float s1z = shs[mm[r] * 4 + 3];
#pragma unroll
            for (int ws = 0; ws < 2; ws++)
#pragma unroll
                for (int b = 0; b < 2; b++) {
                    const int wc = 8 * ws + q2 + b;
                    const float t3 = accT3[r][2 * ws + b];
                    atomicAdd(segp + 32 + 3 * wc + 0, s1x * t3);
                    atomicAdd(segp + 32 + 3 * wc + 1, s1y * t3);
                    atomicAdd(segp + 32 + 3 * wc + 2, s1z * t3);
                }
        }
    }

    // ================= phase 3: j 16..19 (g 64..79) -> V =================
    {
        float accV[4][4][3];
#pragma unroll
        for (int r = 0; r < 4; r++)
#pragma unroll
            for (int i = 0; i < 4; i++)
#pragma unroll
                for (int k = 0; k < 3; k++) accV[r][i][k] = 0.0f;

        for (int j = 16; j < 20; j++) {
            CHUNK_TOP(j);
#pragma unroll
            for (int s = 0; s < 2; s++) {
                CHUNK_MMA_SUB(j, s);
                const int g = 4 * j + 2 * cg + s;
                LOAD_B2V(g);
                const bool is5 = (g >= 72);
                const int u0 = is5 ? 2 * (g - 72) : 2 * (g - 64);
                float av[4][2][3];
#pragma unroll
                for (int r = 0; r < 4; r++) {
#pragma unroll
                    for (int us = 0; us < 2; us++) {
                        const int u = u0 + us;
                        const float xx = x1s[mm[r] * 49 + 3 * u + 0];
                        const float xy = x1s[mm[r] * 49 + 3 * u + 1];
                        const float xz = x1s[mm[r] * 49 + 3 * u + 2];
                        if (!is5) {
                            const float kb = C1IS3 * shs[mm[r] * 4];
                            av[r][us][0] = kb * xx;
                            av[r][us][1] = kb * xy;
                            av[r][us][2] = kb * xz;
                        } else {
                            const float s1x = shs[mm[r] * 4 + 1];
                            const float s1y = shs[mm[r] * 4 + 2];
                            const float s1z = shs[mm[r] * 4 + 3];
                            av[r][us][0] = C1IS6 * (xy * s1z - xz * s1y);
                            av[r][us][1] = C1IS6 * (xz * s1x - xx * s1z);
                            av[r][us][2] = C1IS6 * (xx * s1y - xy * s1x);
                        }
                    }
                }
#pragma unroll
                for (int nt = 0; nt < 4; nt++) {
                    const int us = nt >> 1, ws = nt & 1;
#pragma unroll
                    for (int rt = 0; rt < 2; rt++)
#pragma unroll
                        for (int rr = 0; rr < 2; rr++)
#pragma unroll
                            for (int b = 0; b < 2; b++) {
                                const int r = 2 * rt + rr;
                                const float D = c[rt][nt][2 * rr + b] + b2v[nt][b];
#pragma unroll
                                for (int k = 0; k < 3; k++)
                                    accV[r][2 * ws + b][k] += av[r][us][k] * D;
                            }
                }
            }
        }
#pragma unroll
        for (int r = 0; r < 4; r++) {
            float* segp = g_seg + (size_t)srcs[mm[r]] * NODE_DIM;
#pragma unroll
            for (int ws = 0; ws < 2; ws++)
#pragma unroll
                for (int b = 0; b < 2; b++) {
                    const int wc = 8 * ws + q2 + b;
#pragma unroll
                    for (int k = 0; k < 3; k++)
                        atomicAdd(segp + 32 + 3 * wc + k, accV[r][2 * ws + b][k]);
                }
        }
    }
}

// ---------------- node epilogue ----------------
__global__ void node_kernel(const float* __restrict__ node_attr,
                            const float* __restrict__ mean_shift,
                            const float* __restrict__ aw,
                            const float* __restrict__ ab,
                            float* __restrict__ out) {
    const int warp = (blockIdx.x * blockDim.x + threadIdx.x) >> 5;
    const int lane = threadIdx.x & 31;
    if (warp >= N_NODES) return;
    const unsigned full = 0xFFFFFFFFu;

    const float inv = 1.0f / fmaxf(g_cnt[warp], 1.0f);
    const float* seg = g_seg + (size_t)warp * NODE_DIM;
    const float* na  = node_attr + (size_t)warp * NODE_DIM;

    float o0 = seg[lane] * inv + na[lane];
    float mval = o0;
#pragma unroll
    for (int off = 16; off; off >>= 1) mval += __shfl_xor_sync(full, mval, off);
    mval *= (1.0f / 32.0f);
    const float f0 = o0 - mval * mean_shift[lane];
    float s = f0 * f0;
#pragma unroll
    for (int off = 16; off; off >>= 1) s += __shfl_xor_sync(full, s, off);
    const float sc0 = rsqrtf(s * (1.0f / 32.0f) + EPS_LN) * aw[lane];
    out[(size_t)warp * NODE_DIM + lane] = f0 * sc0 + ab[lane];

    float vx = 0.0f, vy = 0.0f, vz = 0.0f, msv = 0.0f;
    if (lane < 16) {
        vx = seg[32 + 3 * lane + 0] * inv + na[32 + 3 * lane + 0];
        vy = seg[32 + 3 * lane + 1] * inv + na[32 + 3 * lane + 1];
        vz = seg[32 + 3 * lane + 2] * inv + na[32 + 3 * lane + 2];
        msv = mean_shift[32 + lane];
    }
    float mx = vx, my = vy, mz = vz;
#pragma unroll
    for (int off = 16; off; off >>= 1) {
        mx += __shfl_xor_sync(full, mx, off);
        my += __shfl_xor_sync(full, my, off);
        mz += __shfl_xor_sync(full, mz, off);
    }
    mx *= (1.0f / 16.0f); my *= (1.0f / 16.0f); mz *= (1.0f / 16.0f);
    const float fx = vx - mx * msv;
    const float fy = vy - my * msv;
    const float fz = vz - mz * msv;
    float sq = (lane < 16) ? (fx * fx + fy * fy + fz * fz) : 0.0f;
#pragma unroll
    for (int off = 16; off; off >>= 1) sq += __shfl_xor_sync(full, sq, off);
    if (lane < 16) {
        const float sc1 = rsqrtf(sq * (1.0f / 48.0f) + EPS_LN) * aw[32 + lane];
        out[(size_t)warp * NODE_DIM + 32 + 3 * lane + 0] = fx * sc1;
        out[(size_t)warp * NODE_DIM + 32 + 3 * lane + 1] = fy * sc1;
        out[(size_t)warp * NODE_DIM + 32 + 3 * lane + 2] = fz * sc1;
    }
}

// ---------------- launch ----------------
extern "C" void kernel_launch(void* const* d_in, const int* in_sizes, int n_in,
                              void* d_out, int out_size) {
    const float* node_attr  = (const float*)d_in[0];
    const float* edge_attr  = (const float*)d_in[1];
    const float* edge_sh    = (const float*)d_in[2];
    const float* fc_w1      = (const float*)d_in[3];
    const float* fc_b1      = (const float*)d_in[4];
    const float* fc_w2      = (const float*)d_in[5];
    const float* fc_b2      = (const float*)d_in[6];
    const float* mean_shift = (const float*)d_in[7];
    const float* aw         = (const float*)d_in[8];
    const float* ab         = (const float*)d_in[9];
    const int*   edge_index = (const int*)d_in[10];
    float* out = (float*)d_out;

    cudaFuncSetAttribute(gemm1_kernel, cudaFuncAttributeMaxDynamicSharedMemorySize, (int)G1_SMEM);
    cudaFuncSetAttribute(edge_kernel,  cudaFuncAttributeMaxDynamicSharedMemorySize, (int)EDGE_SMEM);

    gemm1_kernel<<<N_EDGES / 128, 256, G1_SMEM>>>(edge_attr, fc_w1, fc_b1, fc_w2);
    edge_kernel<<<NTILES, 256, EDGE_SMEM>>>(node_attr, edge_sh, fc_b2, edge_index);
    node_kernel<<<(N_NODES * 32 + 255) / 256, 256>>>(node_attr, mean_shift, aw, ab, out);
}

// round 9
// speedup vs baseline: 1.5675x; 1.5675x over previous
#include <cuda_runtime.h>
#include <cuda_fp16.h>
#include <cstdint>
#include <cstddef>

#define N_NODES 20000
#define N_EDGES 160000
#define MUL0 32
#define MUL1 16
#define NODE_DIM 80
#define EDGE_FEAT 128
#define HIDDEN 128
#define W_NUMEL 2560
#define MTILE 128
#define NTILES (N_EDGES / MTILE)      // 1250
#define NCHUNK 64
#define NCHUNKS (W_NUMEL / NCHUNK)    // 40

#define C0f   0.14433756729740643f
#define C1f   0.21650635094610965f
#define IS3f  0.5773502691896258f
#define IS6f  0.40824829046386296f
#define C0IS3 (C0f * IS3f)
#define C1IS3 (C1f * IS3f)
#define C1IS6 (C1f * IS6f)
#define EPS_LN 1e-5f

// ---------------- device scratch ----------------
__device__ __align__(16) __half g_A[(size_t)N_EDGES * HIDDEN];     // h fp16, [e][k]
__device__ __align__(16) __half g_Bf16[(size_t)W_NUMEL * HIDDEN];  // W2^T fp16 [n][k]
__device__ float g_seg[(size_t)N_NODES * NODE_DIM];
__device__ float g_cnt[N_NODES];

// ---------------- PTX helpers ----------------
__device__ __forceinline__ uint32_t smem_u32(const void* p) {
    uint32_t a;
    asm("{ .reg .u64 t; cvta.to.shared.u64 t, %1; cvt.u32.u64 %0, t; }" : "=r"(a) : "l"(p));
    return a;
}
__device__ __forceinline__ void ldsm_x4(uint32_t* r, uint32_t addr) {
    asm volatile("ldmatrix.sync.aligned.m8n8.x4.shared.b16 {%0,%1,%2,%3}, [%4];"
        : "=r"(r[0]), "=r"(r[1]), "=r"(r[2]), "=r"(r[3]) : "r"(addr));
}
__device__ __forceinline__ void mma_f16(float* c, const uint32_t* a, uint32_t b0, uint32_t b1) {
    asm volatile("mma.sync.aligned.m16n8k16.row.col.f32.f16.f16.f32 "
        "{%0,%1,%2,%3}, {%4,%5,%6,%7}, {%8,%9}, {%0,%1,%2,%3};"
        : "+f"(c[0]), "+f"(c[1]), "+f"(c[2]), "+f"(c[3])
        : "r"(a[0]), "r"(a[1]), "r"(a[2]), "r"(a[3]), "r"(b0), "r"(b1));
}
__device__ __forceinline__ void cp_async16(uint32_t smem_addr, const void* gptr) {
    asm volatile("cp.async.ca.shared.global [%0], [%1], 16;" :: "r"(smem_addr), "l"(gptr));
}
#define CP_COMMIT() asm volatile("cp.async.commit_group;" ::: "memory")
#define CP_WAIT_0() asm volatile("cp.async.wait_group 0;" ::: "memory")

#define ROWB 272

// ---------------- GEMM1 (fp16 2-pass A hi/lo) + embedded prep (r6 champion, unchanged) ----------------
#define G1_AHI 0
#define G1_ALO 34816
#define G1_W   69632
#define G1_B1  104448
#define G1_SMEM 104960

__global__ __launch_bounds__(256, 2)
void gemm1_kernel(const float* __restrict__ edge_attr,
                  const float* __restrict__ fc_w1,
                  const float* __restrict__ fc_b1,
                  const float* __restrict__ fc_w2) {
    extern __shared__ char smc[];
    const uint32_t smb = smem_u32(smc);
    const int tid = threadIdx.x;
    const int w = tid >> 5;
    const int lane = tid & 31;
    const int e0 = blockIdx.x * 128;

    // embedded prep (block-strided)
    {
        const int gt = blockIdx.x * 256 + tid;
        const int gs = gridDim.x * 256;
        for (int i = gt; i < N_NODES * NODE_DIM; i += gs) g_seg[i] = 0.0f;
        for (int i = gt; i < N_NODES; i += gs) g_cnt[i] = 0.0f;
        for (int i = gt; i < HIDDEN * W_NUMEL; i += gs) {
            const int n = i >> 7, k = i & 127;
            g_Bf16[i] = __float2half_rn(fc_w2[(size_t)k * W_NUMEL + n]);
        }
    }

    // W1 fp32 -> fp16 transposed into SMEM
    for (int i = tid; i < HIDDEN * HIDDEN; i += 256) {
        const int k = i >> 7, n = i & 127;
        *(__half*)(smc + G1_W + n * ROWB + k * 2) = __float2half_rn(fc_w1[i]);
    }

    // stage A: fp32 -> fp16 hi/lo
    const float4* ga = (const float4*)(edge_attr + (size_t)e0 * EDGE_FEAT);
#pragma unroll
    for (int it = 0; it < 16; it++) {
        const int i = tid + it * 256;
        const int row = i >> 5, kc4 = i & 31;
        const float4 v = ga[i];
        const __half hx = __float2half_rn(v.x), hy = __float2half_rn(v.y);
        const __half hz = __float2half_rn(v.z), hw = __float2half_rn(v.w);
        const __half lx = __float2half_rn(v.x - __half2float(hx));
        const __half ly = __float2half_rn(v.y - __half2float(hy));
        const __half lz = __float2half_rn(v.z - __half2float(hz));
        const __half lw = __float2half_rn(v.w - __half2float(hw));
        char* dh = smc + G1_AHI + row * ROWB + kc4 * 8;
        char* dl = smc + G1_ALO + row * ROWB + kc4 * 8;
        *(__half2*)(dh)     = __halves2half2(hx, hy);
        *(__half2*)(dh + 4) = __halves2half2(hz, hw);
        *(__half2*)(dl)     = __halves2half2(lx, ly);
        *(__half2*)(dl + 4) = __halves2half2(lz, lw);
    }
    if (tid < 128) ((float*)(smc + G1_B1))[tid] = fc_b1[tid];
    __syncthreads();

    const int q2 = 2 * (lane & 3);
    const int r8 = lane >> 2;
    const int mA = 16 * w + r8;

    const uint32_t aRow = (uint32_t)(16 * w + (lane & 7) + ((lane >> 3) & 1) * 8);
    const uint32_t aK = (uint32_t)(((lane >> 4) & 1) * 16);
    const uint32_t aHiB = smb + G1_AHI + aRow * ROWB + aK;
    const uint32_t aLoB = smb + G1_ALO + aRow * ROWB + aK;
    const uint32_t bRow = (uint32_t)((lane & 7) + ((lane >> 4) & 1) * 8);
    const uint32_t bK = (uint32_t)(((lane >> 3) & 1) * 16);
    const uint32_t wB = smb + G1_W + bRow * ROWB + bK;

    float c[16][4];
#pragma unroll
    for (int t = 0; t < 16; t++)
#pragma unroll
        for (int i = 0; i < 4; i++) c[t][i] = 0.0f;

#pragma unroll
    for (int ks = 0; ks < 8; ks++) {
        uint32_t ah[4], al[4];
        ldsm_x4(ah, aHiB + ks * 32);
        ldsm_x4(al, aLoB + ks * 32);
#pragma unroll
        for (int tp = 0; tp < 8; tp++) {
            uint32_t wf[4];
            ldsm_x4(wf, wB + tp * (16 * ROWB) + ks * 32);
            mma_f16(c[2 * tp],     ah, wf[0], wf[1]);
            mma_f16(c[2 * tp],     al, wf[0], wf[1]);
            mma_f16(c[2 * tp + 1], ah, wf[2], wf[3]);
            mma_f16(c[2 * tp + 1], al, wf[2], wf[3]);
        }
    }

    const float* b1s = (const float*)(smc + G1_B1);
#pragma unroll
    for (int t = 0; t < 16; t++) {
        const int col = 8 * t + q2;
        const float bb0 = b1s[col], bb1 = b1s[col + 1];
#pragma unroll
        for (int rr = 0; rr < 2; rr++) {
            const int mm = mA + 8 * rr;
            const float v0 = fmaxf(c[t][2 * rr + 0] + bb0, 0.0f);
            const float v1 = fmaxf(c[t][2 * rr + 1] + bb1, 0.0f);
            *(__half2*)(g_A + (size_t)(e0 + mm) * HIDDEN + col) =
                __halves2half2(__float2half_rn(v0), __float2half_rn(v1));
        }
    }
}

// ---------------- edge kernel (r6 config; phase-split loops, phased accs) ----------------
// smem: A[128][272]@0 (34816), B 2x[64][272]@34816 (34816),
//       x0s@69632 (16896), x1s@86528 (25088), shs@111616 (2048), srcs@113664 (512) => 114176
#define OFF_A   0
#define OFF_B   34816
#define BBUF    17408
#define OFF_X0  69632
#define OFF_X1  86528
#define OFF_SH  111616
#define OFF_SRC 113664
#define EDGE_SMEM 114176

// per-chunk top: drain, barrier, prefetch next chunk
#define CHUNK_TOP(j) \
    CP_WAIT_0(); \
    __syncthreads(); \
    if ((j) + 1 < NCHUNKS) { \
        const uint32_t sb = smb + OFF_B + (uint32_t)((((j) + 1) & 1) * BBUF); \
        const __half* gp0 = g_Bf16 + (size_t)((j) + 1) * NCHUNK * HIDDEN; \
        _Pragma("unroll") \
        for (int it = 0; it < 4; it++) { \
            const int i = tid + it * 256; \
            const int row = i >> 4, kc = i & 15; \
            cp_async16(sb + row * ROWB + kc * 16, gp0 + (size_t)row * HIDDEN + kc * 8); \
        } \
        CP_COMMIT(); \
    }

// bias prefetch for both groups of chunk j (issued before MMA; latency hidden)
#define LOAD_B2V8(j) \
    float b2v[8][2]; \
    _Pragma("unroll") for (int tt8 = 0; tt8 < 8; tt8++) { \
        const float2 bv = __ldg((const float2*)(fc_b2 + 64 * (j) + 8 * tt8 + q2)); \
        b2v[tt8][0] = bv.x; b2v[tt8][1] = bv.y; \
    }

// full 16x64 MMA for chunk j: issue every mma before any c read
#define CHUNK_MMA(j) \
    float c[8][4]; \
    { \
        _Pragma("unroll") for (int t = 0; t < 8; t++) \
        _Pragma("unroll") for (int i = 0; i < 4; i++) c[t][i] = 0.0f; \
        const uint32_t bb = bBase0 + (uint32_t)(((j) & 1) * BBUF); \
        _Pragma("unroll") for (int ks = 0; ks < 8; ks++) { \
            uint32_t ah[4]; \
            ldsm_x4(ah, aB + ks * 32); \
            _Pragma("unroll") for (int tp = 0; tp < 4; tp++) { \
                uint32_t bf[4]; \
                ldsm_x4(bf, bb + tp * (16 * ROWB) + ks * 32); \
                mma_f16(c[2 * tp],     ah, bf[0], bf[1]); \
                mma_f16(c[2 * tp + 1], ah, bf[2], bf[3]); \
            } \
        } \
    }

__global__ __launch_bounds__(256, 2)
void edge_kernel(const float* __restrict__ node_attr,
                 const float* __restrict__ edge_sh,
                 const float* __restrict__ fc_b2,
                 const int*   __restrict__ edge_index) {
    extern __shared__ char smc[];
    const uint32_t smb = smem_u32(smc);
    float* x0s = (float*)(smc + OFF_X0);
    float* x1s = (float*)(smc + OFF_X1);
    float* shs = (float*)(smc + OFF_SH);
    int*  srcs = (int*)(smc + OFF_SRC);

    const int tid  = threadIdx.x;
    const int w    = tid >> 5;          // warp -> rows 16w..16w+15
    const int lane = tid & 31;
    const int e0 = blockIdx.x * MTILE;

    // prologue cp.async: B chunk0 + A tile
#pragma unroll
    for (int it = 0; it < 4; it++) {
        const int i = tid + it * 256;
        const int row = i >> 4, kc = i & 15;
        cp_async16(smb + OFF_B + row * ROWB + kc * 16,
                   g_Bf16 + (size_t)row * HIDDEN + kc * 8);
    }
#pragma unroll
    for (int it = 0; it < 8; it++) {
        const int i = tid + it * 256;
        const int row = i >> 4, kc = i & 15;
        cp_async16(smb + OFF_A + row * ROWB + kc * 16,
                   g_A + (size_t)(e0 + row) * HIDDEN + kc * 8);
    }
    CP_COMMIT();

    // gather per-edge vectors
    if (tid < MTILE) {
        const int eg  = e0 + tid;
        const int src = edge_index[eg];
        const int dst = edge_index[N_EDGES + eg];
        srcs[tid] = src;
        atomicAdd(&g_cnt[src], 1.0f);
        const float4* na = (const float4*)(node_attr + (size_t)dst * NODE_DIM);
#pragma unroll
        for (int q = 0; q < 8; q++) {
            const float4 v = na[q];
            x0s[tid * 33 + 4 * q + 0] = v.x;
            x0s[tid * 33 + 4 * q + 1] = v.y;
            x0s[tid * 33 + 4 * q + 2] = v.z;
            x0s[tid * 33 + 4 * q + 3] = v.w;
        }
#pragma unroll
        for (int q = 0; q < 12; q++) {
            const float4 v = na[8 + q];
            x1s[tid * 49 + 4 * q + 0] = v.x;
            x1s[tid * 49 + 4 * q + 1] = v.y;
            x1s[tid * 49 + 4 * q + 2] = v.z;
            x1s[tid * 49 + 4 * q + 3] = v.w;
        }
        const float4 sh4 = *(const float4*)(edge_sh + (size_t)eg * 4);
        shs[tid * 4 + 0] = sh4.x;
        shs[tid * 4 + 1] = sh4.y;
        shs[tid * 4 + 2] = sh4.z;
        shs[tid * 4 + 3] = sh4.w;
    }

    const int q2 = 2 * (lane & 3);
    const int r8 = lane >> 2;
    const int mA = 16 * w + r8;            // rows mA, mA+8

    const uint32_t aRow = (uint32_t)(16 * w + (lane & 7) + ((lane >> 3) & 1) * 8);
    const uint32_t aK = (uint32_t)(((lane >> 4) & 1) * 16);
    const uint32_t aB = smb + OFF_A + aRow * ROWB + aK;
    const uint32_t bRow = (uint32_t)((lane & 7) + ((lane >> 4) & 1) * 8);
    const uint32_t bK = (uint32_t)(((lane >> 3) & 1) * 16);
    const uint32_t bBase0 = smb + OFF_B + bRow * ROWB + bK;

    // per-thread-row constants (valid after the first CHUNK_TOP barrier)
    float sh0r[2] = {0.f, 0.f}, sh1r[2][3] = {{0.f,0.f,0.f},{0.f,0.f,0.f}};
    bool shLoaded = false;
#define LOAD_SH() \
    if (!shLoaded) { \
        _Pragma("unroll") for (int rr = 0; rr < 2; rr++) { \
            const int mmr = mA + 8 * rr; \
            sh0r[rr] = shs[mmr * 4 + 0]; \
            sh1r[rr][0] = shs[mmr * 4 + 1]; \
            sh1r[rr][1] = shs[mmr * 4 + 2]; \
            sh1r[rr][2] = shs[mmr * 4 + 3]; \
        } \
        shLoaded = true; \
    }

    // ============ phase 1a: j 0..15, block1 -> accO ============
    float accO[2][8];
#pragma unroll
    for (int rr = 0; rr < 2; rr++)
#pragma unroll
        for (int i = 0; i < 8; i++) accO[rr][i] = 0.0f;

    for (int j = 0; j < 16; j++) {
        CHUNK_TOP(j);
        LOAD_SH();
        LOAD_B2V8(j);
        CHUNK_MMA(j);
#pragma unroll
        for (int gi = 0; gi < 2; gi++) {
            const int g = 2 * j + gi;
            float s[2];
#pragma unroll
            for (int rr = 0; rr < 2; rr++)
                s[rr] = C0f * sh0r[rr] * x0s[(mA + 8 * rr) * 33 + g];
#pragma unroll
            for (int tt = 0; tt < 4; tt++) {
                float* cc = c[4 * gi + tt];
                const float b0 = b2v[4 * gi + tt][0], b1 = b2v[4 * gi + tt][1];
                accO[0][2 * tt]     += s[0] * (cc[0] + b0);
                accO[0][2 * tt + 1] += s[0] * (cc[1] + b1);
                accO[1][2 * tt]     += s[1] * (cc[2] + b0);
                accO[1][2 * tt + 1] += s[1] * (cc[3] + b1);
            }
        }
    }

    // ============ phase 1b: j 16..23, block2 -> accO ============
    for (int j = 16; j < 24; j++) {
        CHUNK_TOP(j);
        LOAD_B2V8(j);
        CHUNK_MMA(j);
#pragma unroll
        for (int gi = 0; gi < 2; gi++) {
            const int u = 2 * j + gi - 32;
            float s[2];
#pragma unroll
            for (int rr = 0; rr < 2; rr++) {
                const int mmr = mA + 8 * rr;
                s[rr] = C0IS3 * (x1s[mmr * 49 + 3 * u]     * sh1r[rr][0]
                               + x1s[mmr * 49 + 3 * u + 1] * sh1r[rr][1]
                               + x1s[mmr * 49 + 3 * u + 2] * sh1r[rr][2]);
            }
#pragma unroll
            for (int tt = 0; tt < 4; tt++) {
                float* cc = c[4 * gi + tt];
                const float b0 = b2v[4 * gi + tt][0], b1 = b2v[4 * gi + tt][1];
                accO[0][2 * tt]     += s[0] * (cc[0] + b0);
                accO[0][2 * tt + 1] += s[0] * (cc[1] + b1);
                accO[1][2 * tt]     += s[1] * (cc[2] + b0);
                accO[1][2 * tt + 1] += s[1] * (cc[3] + b1);
            }
        }
    }
    // scatter out0
#pragma unroll
    for (int rr = 0; rr < 2; rr++) {
        float* segp = g_seg + (size_t)srcs[mA + 8 * rr] * NODE_DIM;
#pragma unroll
        for (int tt = 0; tt < 4; tt++)
#pragma unroll
            for (int b = 0; b < 2; b++)
                atomicAdd(segp + 8 * tt + q2 + b, accO[rr][2 * tt + b]);
    }

    // ============ phase 2: j 24..31, block3 -> t3 ============
    {
        float accT3[2][4];
#pragma unroll
        for (int rr = 0; rr < 2; rr++)
#pragma unroll
            for (int i = 0; i < 4; i++) accT3[rr][i] = 0.0f;

        for (int j = 24; j < 32; j++) {
            CHUNK_TOP(j);
            LOAD_B2V8(j);
            CHUNK_MMA(j);
#pragma unroll
            for (int gi = 0; gi < 2; gi++) {
                const int g = 2 * j + gi;
                const int u0 = 2 * (g - 48);
                float s[2][2];
#pragma unroll
                for (int rr = 0; rr < 2; rr++) {
                    const int mmr = mA + 8 * rr;
                    s[rr][0] = C1IS3 * x0s[mmr * 33 + u0];
                    s[rr][1] = C1IS3 * x0s[mmr * 33 + u0 + 1];
                }
#pragma unroll
                for (int tt = 0; tt < 4; tt++) {
                    const int us = tt >> 1;
                    const int sl = 2 * (tt & 1);
                    float* cc = c[4 * gi + tt];
                    const float b0 = b2v[4 * gi + tt][0], b1 = b2v[4 * gi + tt][1];
                    accT3[0][sl]     += s[0][us] * (cc[0] + b0);
                    accT3[0][sl + 1] += s[0][us] * (cc[1] + b1);
                    accT3[1][sl]     += s[1][us] * (cc[2] + b0);
                    accT3[1][sl + 1] += s[1][us] * (cc[3] + b1);
                }
            }
        }
        // scatter sh1 * t3
#pragma unroll
        for (int rr = 0; rr < 2; rr++) {
            float* segp = g_seg + (size_t)srcs[mA + 8 * rr] * NODE_DIM;
#pragma unroll
            for (int ws = 0; ws < 2; ws++)
#pragma unroll
                for (int b = 0; b < 2; b++) {
                    const int wc = 8 * ws + q2 + b;
                    const float t3 = accT3[rr][2 * ws + b];
                    atomicAdd(segp + 32 + 3 * wc + 0, sh1r[rr][0] * t3);
                    atomicAdd(segp + 32 + 3 * wc + 1, sh1r[rr][1] * t3);
                    atomicAdd(segp + 32 + 3 * wc + 2, sh1r[rr][2] * t3);
                }
        }
    }

    // ============ phase 3: j 32..39, block4/5 -> V ============
    {
        float accV[2][4][3];
#pragma unroll
        for (int rr = 0; rr < 2; rr++)
#pragma unroll
            for (int i = 0; i < 4; i++)
#pragma unroll
                for (int k = 0; k < 3; k++) accV[rr][i][k] = 0.0f;

        for (int j = 32; j < 40; j++) {
            CHUNK_TOP(j);
            LOAD_B2V8(j);
            CHUNK_MMA(j);
#pragma unroll
            for (int gi = 0; gi < 2; gi++) {
                const int g = 2 * j + gi;
                const bool is5 = (g >= 72);
                const int u0 = is5 ? 2 * (g - 72) : 2 * (g - 64);
                float av[2][2][3];
#pragma unroll
                for (int rr = 0; rr < 2; rr++) {
                    const int mmr = mA + 8 * rr;
#pragma unroll
                    for (int us = 0; us < 2; us++) {
                        const int u = u0 + us;
                        const float xx = x1s[mmr * 49 + 3 * u + 0];
                        const float xy = x1s[mmr * 49 + 3 * u + 1];
                        const float xz = x1s[mmr * 49 + 3 * u + 2];
                        if (!is5) {
                            const float kb = C1IS3 * sh0r[rr];
                            av[rr][us][0] = kb * xx;
                            av[rr][us][1] = kb * xy;
                            av[rr][us][2] = kb * xz;
                        } else {
                            av[rr][us][0] = C1IS6 * (xy * sh1r[rr][2] - xz * sh1r[rr][1]);
                            av[rr][us][1] = C1IS6 * (xz * sh1r[rr][0] - xx * sh1r[rr][2]);
                            av[rr][us][2] = C1IS6 * (xx * sh1r[rr][1] - xy * sh1r[rr][0]);
                        }
                    }
                }
#pragma unroll
                for (int tt = 0; tt < 4; tt++) {
                    const int us = tt >> 1;
                    const int sl = 2 * (tt & 1);
                    float* cc = c[4 * gi + tt];
                    const float b0 = b2v[4 * gi + tt][0], b1 = b2v[4 * gi + tt][1];
                    const float D00 = cc[0] + b0, D01 = cc[1] + b1;
                    const float D10 = cc[2] + b0, D11 = cc[3] + b1;
#pragma unroll
                    for (int k = 0; k < 3; k++) {
                        accV[0][sl][k]     += av[0][us][k] * D00;
                        accV[0][sl + 1][k] += av[0][us][k] * D01;
                        accV[1][sl][k]     += av[1][us][k] * D10;
                        accV[1][sl + 1][k] += av[1][us][k] * D11;
                    }
                }
            }
        }
        // scatter V
#pragma unroll
        for (int rr = 0; rr < 2; rr++) {
            float* segp = g_seg + (size_t)srcs[mA + 8 * rr] * NODE_DIM;
#pragma unroll
            for (int ws = 0; ws < 2; ws++)
#pragma unroll
                for (int b = 0; b < 2; b++) {
                    const int wc = 8 * ws + q2 + b;
#pragma unroll
                    for (int k = 0; k < 3; k++)
                        atomicAdd(segp + 32 + 3 * wc + k, accV[rr][2 * ws + b][k]);
                }
        }
    }
}

// ---------------- node epilogue ----------------
__global__ void node_kernel(const float* __restrict__ node_attr,
                            const float* __restrict__ mean_shift,
                            const float* __restrict__ aw,
                            const float* __restrict__ ab,
                            float* __restrict__ out) {
    const int warp = (blockIdx.x * blockDim.x + threadIdx.x) >> 5;
    const int lane = threadIdx.x & 31;
    if (warp >= N_NODES) return;
    const unsigned full = 0xFFFFFFFFu;

    const float inv = 1.0f / fmaxf(g_cnt[warp], 1.0f);
    const float* seg = g_seg + (size_t)warp * NODE_DIM;
    const float* na  = node_attr + (size_t)warp * NODE_DIM;

    float o0 = seg[lane] * inv + na[lane];
    float mval = o0;
#pragma unroll
    for (int off = 16; off; off >>= 1) mval += __shfl_xor_sync(full, mval, off);
    mval *= (1.0f / 32.0f);
    const float f0 = o0 - mval * mean_shift[lane];
    float s = f0 * f0;
#pragma unroll
    for (int off = 16; off; off >>= 1) s += __shfl_xor_sync(full, s, off);
    const float sc0 = rsqrtf(s * (1.0f / 32.0f) + EPS_LN) * aw[lane];
    out[(size_t)warp * NODE_DIM + lane] = f0 * sc0 + ab[lane];

    float vx = 0.0f, vy = 0.0f, vz = 0.0f, msv = 0.0f;
    if (lane < 16) {
        vx = seg[32 + 3 * lane + 0] * inv + na[32 + 3 * lane + 0];
        vy = seg[32 + 3 * lane + 1] * inv + na[32 + 3 * lane + 1];
        vz = seg[32 + 3 * lane + 2] * inv + na[32 + 3 * lane + 2];
        msv = mean_shift[32 + lane];
    }
    float mx = vx, my = vy, mz = vz;
#pragma unroll
    for (int off = 16; off; off >>= 1) {
        mx += __shfl_xor_sync(full, mx, off);
        my += __shfl_xor_sync(full, my, off);
        mz += __shfl_xor_sync(full, mz, off);
    }
    mx *= (1.0f / 16.0f); my *= (1.0f / 16.0f); mz *= (1.0f / 16.0f);
    const float fx = vx - mx * msv;
    const float fy = vy - my * msv;
    const float fz = vz - mz * msv;
    float sq = (lane < 16) ? (fx * fx + fy * fy + fz * fz) : 0.0f;
#pragma unroll
    for (int off = 16; off; off >>= 1) sq += __shfl_xor_sync(full, sq, off);
    if (lane < 16) {
        const float sc1 = rsqrtf(sq * (1.0f / 48.0f) + EPS_LN) * aw[32 + lane];
        out[(size_t)warp * NODE_DIM + 32 + 3 * lane + 0] = fx * sc1;
        out[(size_t)warp * NODE_DIM + 32 + 3 * lane + 1] = fy * sc1;
        out[(size_t)warp * NODE_DIM + 32 + 3 * lane + 2] = fz * sc1;
    }
}

// ---------------- launch ----------------
extern "C" void kernel_launch(void* const* d_in, const int* in_sizes, int n_in,
                              void* d_out, int out_size) {
    const float* node_attr  = (const float*)d_in[0];
    const float* edge_attr  = (const float*)d_in[1];
    const float* edge_sh    = (const float*)d_in[2];
    const float* fc_w1      = (const float*)d_in[3];
    const float* fc_b1      = (const float*)d_in[4];
    const float* fc_w2      = (const float*)d_in[5];
    const float* fc_b2      = (const float*)d_in[6];
    const float* mean_shift = (const float*)d_in[7];
    const float* aw         = (const float*)d_in[8];
    const float* ab         = (const float*)d_in[9];
    const int*   edge_index = (const int*)d_in[10];
    float* out = (float*)d_out;

    cudaFuncSetAttribute(gemm1_kernel, cudaFuncAttributeMaxDynamicSharedMemorySize, (int)G1_SMEM);
    cudaFuncSetAttribute(edge_kernel,  cudaFuncAttributeMaxDynamicSharedMemorySize, (int)EDGE_SMEM);

    gemm1_kernel<<<N_EDGES / 128, 256, G1_SMEM>>>(edge_attr, fc_w1, fc_b1, fc_w2);
    edge_kernel<<<NTILES, 256, EDGE_SMEM>>>(node_attr, edge_sh, fc_b2, edge_index);
    node_kernel<<<(N_NODES * 32 + 255) / 256, 256>>>(node_attr, mean_shift, aw, ab, out);
}